// round 7
// baseline (speedup 1.0000x reference)
#include <cuda_runtime.h>
#include <cstdint>

#define T_STEPS 1024
#define B_      64
#define D_      512
#define H_      512

// ---------------- persistent kernel config --------------------
#define G_CTAS   64
#define S_COLS   8
#define NTHREADS 64                   // 2 warps, 32 batch-rows each
#define N_BLK    4                    // k-blocks of 128 h-columns
#define KS_PER_BLK 16

#define WP_FLOATS 16384               // 64 KB recurrent weights (B-fragment order)
#define AS_BLK_FLOATS (B_ * 128)      // 8192 floats = 32 KB per k-block

#define SM_WP_OFF   0
#define SM_AS_OFF   (WP_FLOATS * 4)
#define SMEM_BYTES  (SM_AS_OFF + N_BLK * AS_BLK_FLOATS * 4)   // 196608 B

// ---------------- gemm kernel config --------------------------
#define GM_AS   (128 * 36)
#define GM_BS   (32 * 72)
#define GM_SMEM ((2 * GM_AS + 2 * GM_BS) * 4)

// ---------------- device globals ------------------------------
__device__ __align__(256) float    g_xp[(size_t)T_STEPS * B_ * 4 * H_];
__device__ __align__(256) float    g_hblk[2][N_BLK][AS_BLK_FLOATS];
__device__ __align__(256) unsigned g_flags[G_CTAS * 32];   // one per 128B line

// ---------------- helpers -------------------------------------
__device__ __forceinline__ float tf32r(float x) {
    unsigned r;
    asm("cvt.rna.tf32.f32 %0, %1;" : "=r"(r) : "f"(x));
    return __uint_as_float(r);
}
__device__ __forceinline__ float sigm_(float x) {
    return __fdividef(1.0f, 1.0f + __expf(-x));
}
__device__ __forceinline__ float tanh_(float x) {
    float a = fabsf(x);
    float e = __expf(-2.0f * a);
    float r = __fdividef(1.0f - e, 1.0f + e);
    return copysignf(r, x);
}
__device__ __forceinline__ void mma8(float* acc, unsigned a0, unsigned a1,
                                     unsigned a2, unsigned a3,
                                     unsigned b0, unsigned b1) {
    asm volatile(
        "mma.sync.aligned.m16n8k8.row.col.f32.tf32.tf32.f32 "
        "{%0,%1,%2,%3}, {%4,%5,%6,%7}, {%8,%9}, {%0,%1,%2,%3};"
        : "+f"(acc[0]), "+f"(acc[1]), "+f"(acc[2]), "+f"(acc[3])
        : "r"(a0), "r"(a1), "r"(a2), "r"(a3), "r"(b0), "r"(b1));
}
__device__ __forceinline__ void cp16(unsigned dst, const void* src) {
    asm volatile("cp.async.cg.shared.global [%0], [%1], 16;\n"
                 :: "r"(dst), "l"(src) : "memory");
}
// h storage: within a 128-col block, position kb+2t holds k=kb+t,
// position kb+2t+1 holds k=kb+t+4 (A frag = one LDS.64), then XOR-swizzled
// by (row&7)<<3 for bank-conflict freedom.
__device__ __forceinline__ int hpos(int row, int col) {
    int o = col & 127;
    int j = o & 7;
    int p = (o & ~7) | ((j < 4) ? (2 * j) : (2 * (j - 4) + 1));
    return row * 128 + (p ^ ((row & 7) << 3));
}

// ---------------- init ----------------------------------------
__global__ void lstm_init(const float* __restrict__ h0) {
    unsigned tid  = blockIdx.x * blockDim.x + threadIdx.x;
    unsigned nthr = gridDim.x * blockDim.x;
    for (unsigned i = tid; i < G_CTAS * 32; i += nthr) g_flags[i] = 0;
    for (unsigned i = tid; i < B_ * H_; i += nthr) {
        int row = i >> 9, col = i & 511;
        g_hblk[0][col >> 7][hpos(row, col)] = tf32r(h0[i]);
    }
}

// ---------------- x-projection GEMM (R4-proven) ---------------
__global__ void __launch_bounds__(256)
xproj_gemm(const float* __restrict__ x,
           const float* __restrict__ Wii, const float* __restrict__ Wif,
           const float* __restrict__ Wig, const float* __restrict__ Wio,
           const float* __restrict__ bi,  const float* __restrict__ bf,
           const float* __restrict__ bg,  const float* __restrict__ bo)
{
    extern __shared__ float sm[];
    float* As = sm;
    float* Bs = sm + 2 * GM_AS;

    const int tid  = threadIdx.x;
    const int lane = tid & 31;
    const int wid  = tid >> 5;
    const int wm   = wid & 3;
    const int wn   = wid >> 2;
    const int g    = lane >> 2;
    const int t    = lane & 3;

    const int nb = blockIdx.x * 64;
    const int mb = blockIdx.y * 128;
    const int gate = nb >> 9;
    const int colb = nb & 511;

    const float* Wg = (gate == 0) ? Wii : (gate == 1) ? Wif : (gate == 2) ? Wig : Wio;
    const float* bv = (gate == 0) ? bi  : (gate == 1) ? bf  : (gate == 2) ? bg  : bo;

    float acc[2][4][4];
    #pragma unroll
    for (int nt4 = 0; nt4 < 4; ++nt4) {
        float b0 = bv[colb + wn * 32 + nt4 * 8 + 2 * t];
        float b1 = bv[colb + wn * 32 + nt4 * 8 + 2 * t + 1];
        #pragma unroll
        for (int mt = 0; mt < 2; ++mt) {
            acc[mt][nt4][0] = b0; acc[mt][nt4][1] = b1;
            acc[mt][nt4][2] = b0; acc[mt][nt4][3] = b1;
        }
    }

    float4 ra[4], rb[2];
    auto ldAB = [&](int it) {
        #pragma unroll
        for (int i = 0; i < 4; ++i) {
            int idx = tid + i * 256;
            int row = idx >> 3, j4 = idx & 7;
            ra[i] = *reinterpret_cast<const float4*>(
                x + (size_t)(mb + row) * 512 + it * 32 + j4 * 4);
        }
        #pragma unroll
        for (int i = 0; i < 2; ++i) {
            int idx = tid + i * 256;
            int kr = idx >> 4, j4 = idx & 15;
            rb[i] = *reinterpret_cast<const float4*>(
                Wg + (size_t)(it * 32 + kr) * 512 + colb + j4 * 4);
        }
    };
    auto stAB = [&](int buf) {
        #pragma unroll
        for (int i = 0; i < 4; ++i) {
            int idx = tid + i * 256;
            int row = idx >> 3, j4 = idx & 7;
            float4 v = ra[i];
            v.x = tf32r(v.x); v.y = tf32r(v.y); v.z = tf32r(v.z); v.w = tf32r(v.w);
            *reinterpret_cast<float4*>(As + buf * GM_AS + row * 36 + j4 * 4) = v;
        }
        #pragma unroll
        for (int i = 0; i < 2; ++i) {
            int idx = tid + i * 256;
            int kr = idx >> 4, j4 = idx & 15;
            float4 v = rb[i];
            v.x = tf32r(v.x); v.y = tf32r(v.y); v.z = tf32r(v.z); v.w = tf32r(v.w);
            *reinterpret_cast<float4*>(Bs + buf * GM_BS + kr * 72 + j4 * 4) = v;
        }
    };

    ldAB(0);
    stAB(0);
    __syncthreads();

    #pragma unroll 1
    for (int it = 0; it < 16; ++it) {
        if (it < 15) ldAB(it + 1);
        const float* Ab = As + (it & 1) * GM_AS;
        const float* Bb = Bs + (it & 1) * GM_BS;
        #pragma unroll
        for (int ks = 0; ks < 4; ++ks) {
            const int kb = ks * 8;
            unsigned a[2][4], b[4][2];
            #pragma unroll
            for (int mt = 0; mt < 2; ++mt) {
                int rowb = wm * 32 + mt * 16;
                a[mt][0] = __float_as_uint(Ab[(rowb + g)     * 36 + kb + t]);
                a[mt][1] = __float_as_uint(Ab[(rowb + g + 8) * 36 + kb + t]);
                a[mt][2] = __float_as_uint(Ab[(rowb + g)     * 36 + kb + t + 4]);
                a[mt][3] = __float_as_uint(Ab[(rowb + g + 8) * 36 + kb + t + 4]);
            }
            #pragma unroll
            for (int nt4 = 0; nt4 < 4; ++nt4) {
                int cb = wn * 32 + nt4 * 8 + g;
                b[nt4][0] = __float_as_uint(Bb[(kb + t)     * 72 + cb]);
                b[nt4][1] = __float_as_uint(Bb[(kb + t + 4) * 72 + cb]);
            }
            #pragma unroll
            for (int mt = 0; mt < 2; ++mt)
                #pragma unroll
                for (int nt4 = 0; nt4 < 4; ++nt4)
                    mma8(acc[mt][nt4], a[mt][0], a[mt][1], a[mt][2], a[mt][3],
                         b[nt4][0], b[nt4][1]);
        }
        if (it < 15) {
            stAB((it + 1) & 1);
            __syncthreads();
        }
    }

    #pragma unroll
    for (int mt = 0; mt < 2; ++mt) {
        #pragma unroll
        for (int nt4 = 0; nt4 < 4; ++nt4) {
            int row0 = mb + wm * 32 + mt * 16 + g;
            int col  = nb + wn * 32 + nt4 * 8 + 2 * t;
            *reinterpret_cast<float2*>(g_xp + (size_t)row0 * 2048 + col) =
                make_float2(acc[mt][nt4][0], acc[mt][nt4][1]);
            *reinterpret_cast<float2*>(g_xp + (size_t)(row0 + 8) * 2048 + col) =
                make_float2(acc[mt][nt4][2], acc[mt][nt4][3]);
        }
    }
}

// ---------------- persistent LSTM kernel (2 warps) ------------
__global__ void __launch_bounds__(NTHREADS, 1)
lstm_persist(const float* __restrict__ c0,
             const float* __restrict__ Whi, const float* __restrict__ Whf,
             const float* __restrict__ Whg, const float* __restrict__ Who,
             float* __restrict__ out)
{
    extern __shared__ char smem_raw[];
    float* Wp  = reinterpret_cast<float*>(smem_raw + SM_WP_OFF);
    float* Asb = reinterpret_cast<float*>(smem_raw + SM_AS_OFF);

    const int tid  = threadIdx.x;
    const int wid  = tid >> 5;         // 0 or 1: batch rows [wid*32, wid*32+32)
    const int lane = tid & 31;
    const int g    = lane >> 2;
    const int t    = lane & 3;
    const int cta  = blockIdx.x;

    const unsigned as_base = (unsigned)__cvta_generic_to_shared(smem_raw) + SM_AS_OFF;

    // one-time: stage recurrent weight slice, tf32, B-fragment order
    {
        const float* Wh[4] = {Whi, Whf, Whg, Who};
        for (int e = tid; e < WP_FLOATS; e += NTHREADS) {
            int j   = e & 1;
            int ln  = (e >> 1) & 31;
            int nt  = (e >> 6) & 3;
            int ksg = e >> 8;
            int jj  = ln >> 2;
            int k   = ksg * 8 + (ln & 3) + 4 * j;
            int col = cta * S_COLS + jj;
            Wp[e] = tf32r(Wh[nt][k * H_ + col]);
        }
    }

    const int col0 = cta * S_COLS + 2 * t;
    const int rbase = wid * 32 + g;          // rows: rbase + {0,8,16,24}
    float creg[2][4];
    #pragma unroll
    for (int mt = 0; mt < 2; ++mt) {
        int rA = rbase + mt * 16, rB = rA + 8;
        creg[mt][0] = c0[rA * H_ + col0];
        creg[mt][1] = c0[rA * H_ + col0 + 1];
        creg[mt][2] = c0[rB * H_ + col0];
        creg[mt][3] = c0[rB * H_ + col0 + 1];
    }

    // prefetch x_proj for step 0
    float2 xpre[2][4][2];
    #pragma unroll
    for (int mt = 0; mt < 2; ++mt) {
        int rA = rbase + mt * 16, rB = rA + 8;
        #pragma unroll
        for (int nt = 0; nt < 4; ++nt) {
            xpre[mt][nt][0] = __ldcs(reinterpret_cast<const float2*>(
                g_xp + (size_t)rA * 2048 + nt * 512 + col0));
            xpre[mt][nt][1] = __ldcs(reinterpret_cast<const float2*>(
                g_xp + (size_t)rB * 2048 + nt * 512 + col0));
        }
    }

    __syncthreads();   // Wp ready

    const unsigned* WpU = reinterpret_cast<const unsigned*>(Wp);
    const int swz = g << 3;

    for (int step = 0; step < T_STEPS; ++step) {
        const float* hsrc = &g_hblk[step & 1][0][0];
        float*       hnext = &g_hblk[(step + 1) & 1][0][0];

        // copy issue for one block: warp wid copies its own 32 rows
        auto issue_blk = [&](int b) {
            const float* src = hsrc + b * AS_BLK_FLOATS;
            unsigned     dst = as_base + (unsigned)b * 32768u;
            #pragma unroll
            for (int i = 0; i < 32; ++i) {
                int q   = i * 32 + lane;              // chunk within warp's 32 rows
                int row = wid * 32 + (q >> 5);
                int pos = (q & 31) * 4;
                cp16(dst + (unsigned)(row * 128 + pos) * 4u,
                     src + row * 128 + pos);
            }
            asm volatile("cp.async.commit_group;\n" ::: "memory");
        };

        issue_blk(0);

        // acc init from prefetched x_proj (bias folded)
        float acc[2][4][4];
        #pragma unroll
        for (int mt = 0; mt < 2; ++mt)
            #pragma unroll
            for (int nt = 0; nt < 4; ++nt) {
                acc[mt][nt][0] = xpre[mt][nt][0].x;
                acc[mt][nt][1] = xpre[mt][nt][0].y;
                acc[mt][nt][2] = xpre[mt][nt][1].x;
                acc[mt][nt][3] = xpre[mt][nt][1].y;
            }

        // prefetch x_proj for step+1 (hidden under mma)
        if (step + 1 < T_STEPS) {
            const float* xpn = g_xp + (size_t)(step + 1) * B_ * 2048;
            #pragma unroll
            for (int mt = 0; mt < 2; ++mt) {
                int rA = rbase + mt * 16, rB = rA + 8;
                #pragma unroll
                for (int nt = 0; nt < 4; ++nt) {
                    xpre[mt][nt][0] = __ldcs(reinterpret_cast<const float2*>(
                        xpn + (size_t)rA * 2048 + nt * 512 + col0));
                    xpre[mt][nt][1] = __ldcs(reinterpret_cast<const float2*>(
                        xpn + (size_t)rB * 2048 + nt * 512 + col0));
                }
            }
        }

        // mma over 4 k-blocks, pipelined copy issue
        #pragma unroll 1
        for (int blk = 0; blk < N_BLK; ++blk) {
            if (blk + 1 < N_BLK) {
                issue_blk(blk + 1);
                asm volatile("cp.async.wait_group 1;\n" ::: "memory");
            } else {
                asm volatile("cp.async.wait_group 0;\n" ::: "memory");
            }
            __syncwarp();
            const float* Ab = Asb + blk * AS_BLK_FLOATS;
            #pragma unroll 4
            for (int ks = 0; ks < KS_PER_BLK; ++ks) {
                const int kb = ks * 8;
                const int ksg = blk * KS_PER_BLK + ks;
                unsigned a[2][4];
                #pragma unroll
                for (int mt = 0; mt < 2; ++mt) {
                    int rA = rbase + mt * 16;
                    float2 aA = *reinterpret_cast<const float2*>(
                        Ab + rA * 128 + ((kb + 2 * t) ^ swz));
                    float2 aB = *reinterpret_cast<const float2*>(
                        Ab + (rA + 8) * 128 + ((kb + 2 * t) ^ swz));
                    a[mt][0] = __float_as_uint(aA.x);
                    a[mt][1] = __float_as_uint(aB.x);
                    a[mt][2] = __float_as_uint(aA.y);
                    a[mt][3] = __float_as_uint(aB.y);
                }
                #pragma unroll
                for (int nt = 0; nt < 4; ++nt) {
                    uint2 b2 = *reinterpret_cast<const uint2*>(
                        WpU + ((size_t)(ksg * 4 + nt) * 32 + lane) * 2);
                    #pragma unroll
                    for (int mt = 0; mt < 2; ++mt)
                        mma8(acc[mt][nt], a[mt][0], a[mt][1], a[mt][2], a[mt][3],
                             b2.x, b2.y);
                }
            }
        }

        // epilogue: gates -> cell -> h (stored permuted/swizzled, L2-direct)
        #pragma unroll
        for (int mt = 0; mt < 2; ++mt) {
            #pragma unroll
            for (int ci = 0; ci < 4; ++ci) {
                const int rb  = rbase + mt * 16 + ((ci >= 2) ? 8 : 0);
                const int col = col0 + (ci & 1);
                float iv = sigm_(acc[mt][0][ci]);
                float fv = sigm_(acc[mt][1][ci]);
                float gv = tanh_(acc[mt][2][ci]);
                float ov = sigm_(acc[mt][3][ci]);
                float c  = fv * creg[mt][ci] + iv * gv;
                creg[mt][ci] = c;
                float h  = ov * tanh_(c);
                __stcg(hnext + (col >> 7) * AS_BLK_FLOATS + hpos(rb, col), tf32r(h));
                if (step == T_STEPS - 1) {
                    out[rb * H_ + col]           = h;
                    out[B_ * H_ + rb * H_ + col] = c;
                }
            }
        }

        // distributed grid barrier: flag write + all-poll (no central release)
        __syncthreads();
        const unsigned want = (unsigned)(step + 1);
        if (tid == 0) {
            __threadfence();
            ((volatile unsigned*)g_flags)[cta * 32] = want;
        }
        {
            volatile unsigned* f = (volatile unsigned*)&g_flags[tid * 32];
            while (*f < want) { }
            __threadfence();
        }
        __syncthreads();
    }
}

// ---------------- launch --------------------------------------
extern "C" void kernel_launch(void* const* d_in, const int* in_sizes, int n_in,
                              void* d_out, int out_size)
{
    const float* x   = (const float*)d_in[0];
    const float* h0  = (const float*)d_in[1];
    const float* c0  = (const float*)d_in[2];
    const float* Wii = (const float*)d_in[3];
    const float* Whi = (const float*)d_in[4];
    const float* bi  = (const float*)d_in[5];
    const float* Wif = (const float*)d_in[6];
    const float* Whf = (const float*)d_in[7];
    const float* bf  = (const float*)d_in[8];
    const float* Wig = (const float*)d_in[9];
    const float* Whg = (const float*)d_in[10];
    const float* bg  = (const float*)d_in[11];
    const float* Wio = (const float*)d_in[12];
    const float* Who = (const float*)d_in[13];
    const float* bo  = (const float*)d_in[14];
    float* out = (float*)d_out;

    static int attr_set = 0;
    if (!attr_set) {
        cudaFuncSetAttribute(lstm_persist,
                             cudaFuncAttributeMaxDynamicSharedMemorySize, SMEM_BYTES);
        cudaFuncSetAttribute(xproj_gemm,
                             cudaFuncAttributeMaxDynamicSharedMemorySize, GM_SMEM);
        attr_set = 1;
    }

    lstm_init<<<64, 256>>>(h0);
    xproj_gemm<<<dim3(32, 512), 256, GM_SMEM>>>(x, Wii, Wif, Wig, Wio,
                                                bi, bf, bg, bo);
    lstm_persist<<<G_CTAS, NTHREADS, SMEM_BYTES>>>(c0, Whi, Whf, Whg, Who, out);
}

// round 8
// speedup vs baseline: 1.3067x; 1.3067x over previous
#include <cuda_runtime.h>
#include <cstdint>

#define T_STEPS 1024
#define B_      64
#define D_      512
#define H_      512

// ---------------- persistent kernel config --------------------
#define G_CTAS   64
#define S_COLS   8
#define NTHREADS 128                  // 4 warps, 16 batch-rows each
#define N_BLK    4                    // k-blocks of 128 h-columns
#define KS_PER_BLK 16

#define WP_FLOATS 16384               // 64 KB recurrent weights (B-fragment order)
#define AS_BLK_FLOATS (B_ * 128)      // 8192 floats = 32 KB per k-block

#define SM_WP_OFF   0
#define SM_AS_OFF   (WP_FLOATS * 4)
#define SMEM_BYTES  (SM_AS_OFF + N_BLK * AS_BLK_FLOATS * 4)   // 196608 B

// ---------------- gemm kernel config --------------------------
#define GM_AS   (128 * 36)
#define GM_BS   (32 * 72)
#define GM_SMEM ((2 * GM_AS + 2 * GM_BS) * 4)

// ---------------- device globals ------------------------------
__device__ __align__(256) float    g_xp[(size_t)T_STEPS * B_ * 4 * H_];
__device__ __align__(256) float    g_hblk[3][N_BLK][AS_BLK_FLOATS];  // triple buffer
__device__ __align__(256) unsigned g_flags[G_CTAS * 32];             // 1 per 128B line

// ---------------- helpers -------------------------------------
__device__ __forceinline__ float tf32r(float x) {
    unsigned r;
    asm("cvt.rna.tf32.f32 %0, %1;" : "=r"(r) : "f"(x));
    return __uint_as_float(r);
}
__device__ __forceinline__ float sigm_(float x) {
    return __fdividef(1.0f, 1.0f + __expf(-x));
}
__device__ __forceinline__ float tanh_(float x) {
    float a = fabsf(x);
    float e = __expf(-2.0f * a);
    float r = __fdividef(1.0f - e, 1.0f + e);
    return copysignf(r, x);
}
__device__ __forceinline__ void mma8(float* acc, unsigned a0, unsigned a1,
                                     unsigned a2, unsigned a3,
                                     unsigned b0, unsigned b1) {
    asm volatile(
        "mma.sync.aligned.m16n8k8.row.col.f32.tf32.tf32.f32 "
        "{%0,%1,%2,%3}, {%4,%5,%6,%7}, {%8,%9}, {%0,%1,%2,%3};"
        : "+f"(acc[0]), "+f"(acc[1]), "+f"(acc[2]), "+f"(acc[3])
        : "r"(a0), "r"(a1), "r"(a2), "r"(a3), "r"(b0), "r"(b1));
}
__device__ __forceinline__ void cp16(unsigned dst, const void* src) {
    asm volatile("cp.async.cg.shared.global [%0], [%1], 16;\n"
                 :: "r"(dst), "l"(src) : "memory");
}
__device__ __forceinline__ unsigned ld_acq(const unsigned* p) {
    unsigned v;
    asm volatile("ld.acquire.gpu.global.u32 %0, [%1];"
                 : "=r"(v) : "l"(p) : "memory");
    return v;
}
__device__ __forceinline__ void st_rel(unsigned* p, unsigned v) {
    asm volatile("st.release.gpu.global.u32 [%0], %1;"
                 :: "l"(p), "r"(v) : "memory");
}
// h storage: within a 128-col block, position kb+2t holds k=kb+t,
// position kb+2t+1 holds k=kb+t+4 (A frag = one LDS.64), XOR-swizzled
// by (row&7)<<3 for bank-conflict reduction. (R7-verified correct.)
__device__ __forceinline__ int hpos(int row, int col) {
    int o = col & 127;
    int j = o & 7;
    int p = (o & ~7) | ((j < 4) ? (2 * j) : (2 * (j - 4) + 1));
    return row * 128 + (p ^ ((row & 7) << 3));
}

// ---------------- init ----------------------------------------
__global__ void lstm_init(const float* __restrict__ h0) {
    unsigned tid  = blockIdx.x * blockDim.x + threadIdx.x;
    unsigned nthr = gridDim.x * blockDim.x;
    for (unsigned i = tid; i < G_CTAS * 32; i += nthr) g_flags[i] = 0;
    for (unsigned i = tid; i < B_ * H_; i += nthr) {
        int row = i >> 9, col = i & 511;
        g_hblk[0][col >> 7][hpos(row, col)] = tf32r(h0[i]);
    }
}

// ---------------- x-projection GEMM (R4-proven) ---------------
__global__ void __launch_bounds__(256)
xproj_gemm(const float* __restrict__ x,
           const float* __restrict__ Wii, const float* __restrict__ Wif,
           const float* __restrict__ Wig, const float* __restrict__ Wio,
           const float* __restrict__ bi,  const float* __restrict__ bf,
           const float* __restrict__ bg,  const float* __restrict__ bo)
{
    extern __shared__ float sm[];
    float* As = sm;
    float* Bs = sm + 2 * GM_AS;

    const int tid  = threadIdx.x;
    const int lane = tid & 31;
    const int wid  = tid >> 5;
    const int wm   = wid & 3;
    const int wn   = wid >> 2;
    const int g    = lane >> 2;
    const int t    = lane & 3;

    const int nb = blockIdx.x * 64;
    const int mb = blockIdx.y * 128;
    const int gate = nb >> 9;
    const int colb = nb & 511;

    const float* Wg = (gate == 0) ? Wii : (gate == 1) ? Wif : (gate == 2) ? Wig : Wio;
    const float* bv = (gate == 0) ? bi  : (gate == 1) ? bf  : (gate == 2) ? bg  : bo;

    float acc[2][4][4];
    #pragma unroll
    for (int nt4 = 0; nt4 < 4; ++nt4) {
        float b0 = bv[colb + wn * 32 + nt4 * 8 + 2 * t];
        float b1 = bv[colb + wn * 32 + nt4 * 8 + 2 * t + 1];
        #pragma unroll
        for (int mt = 0; mt < 2; ++mt) {
            acc[mt][nt4][0] = b0; acc[mt][nt4][1] = b1;
            acc[mt][nt4][2] = b0; acc[mt][nt4][3] = b1;
        }
    }

    float4 ra[4], rb[2];
    auto ldAB = [&](int it) {
        #pragma unroll
        for (int i = 0; i < 4; ++i) {
            int idx = tid + i * 256;
            int row = idx >> 3, j4 = idx & 7;
            ra[i] = *reinterpret_cast<const float4*>(
                x + (size_t)(mb + row) * 512 + it * 32 + j4 * 4);
        }
        #pragma unroll
        for (int i = 0; i < 2; ++i) {
            int idx = tid + i * 256;
            int kr = idx >> 4, j4 = idx & 15;
            rb[i] = *reinterpret_cast<const float4*>(
                Wg + (size_t)(it * 32 + kr) * 512 + colb + j4 * 4);
        }
    };
    auto stAB = [&](int buf) {
        #pragma unroll
        for (int i = 0; i < 4; ++i) {
            int idx = tid + i * 256;
            int row = idx >> 3, j4 = idx & 7;
            float4 v = ra[i];
            v.x = tf32r(v.x); v.y = tf32r(v.y); v.z = tf32r(v.z); v.w = tf32r(v.w);
            *reinterpret_cast<float4*>(As + buf * GM_AS + row * 36 + j4 * 4) = v;
        }
        #pragma unroll
        for (int i = 0; i < 2; ++i) {
            int idx = tid + i * 256;
            int kr = idx >> 4, j4 = idx & 15;
            float4 v = rb[i];
            v.x = tf32r(v.x); v.y = tf32r(v.y); v.z = tf32r(v.z); v.w = tf32r(v.w);
            *reinterpret_cast<float4*>(Bs + buf * GM_BS + kr * 72 + j4 * 4) = v;
        }
    };

    ldAB(0);
    stAB(0);
    __syncthreads();

    #pragma unroll 1
    for (int it = 0; it < 16; ++it) {
        if (it < 15) ldAB(it + 1);
        const float* Ab = As + (it & 1) * GM_AS;
        const float* Bb = Bs + (it & 1) * GM_BS;
        #pragma unroll
        for (int ks = 0; ks < 4; ++ks) {
            const int kb = ks * 8;
            unsigned a[2][4], b[4][2];
            #pragma unroll
            for (int mt = 0; mt < 2; ++mt) {
                int rowb = wm * 32 + mt * 16;
                a[mt][0] = __float_as_uint(Ab[(rowb + g)     * 36 + kb + t]);
                a[mt][1] = __float_as_uint(Ab[(rowb + g + 8) * 36 + kb + t]);
                a[mt][2] = __float_as_uint(Ab[(rowb + g)     * 36 + kb + t + 4]);
                a[mt][3] = __float_as_uint(Ab[(rowb + g + 8) * 36 + kb + t + 4]);
            }
            #pragma unroll
            for (int nt4 = 0; nt4 < 4; ++nt4) {
                int cb = wn * 32 + nt4 * 8 + g;
                b[nt4][0] = __float_as_uint(Bb[(kb + t)     * 72 + cb]);
                b[nt4][1] = __float_as_uint(Bb[(kb + t + 4) * 72 + cb]);
            }
            #pragma unroll
            for (int mt = 0; mt < 2; ++mt)
                #pragma unroll
                for (int nt4 = 0; nt4 < 4; ++nt4)
                    mma8(acc[mt][nt4], a[mt][0], a[mt][1], a[mt][2], a[mt][3],
                         b[nt4][0], b[nt4][1]);
        }
        if (it < 15) {
            stAB((it + 1) & 1);
            __syncthreads();
        }
    }

    #pragma unroll
    for (int mt = 0; mt < 2; ++mt) {
        #pragma unroll
        for (int nt4 = 0; nt4 < 4; ++nt4) {
            int row0 = mb + wm * 32 + mt * 16 + g;
            int col  = nb + wn * 32 + nt4 * 8 + 2 * t;
            *reinterpret_cast<float2*>(g_xp + (size_t)row0 * 2048 + col) =
                make_float2(acc[mt][nt4][0], acc[mt][nt4][1]);
            *reinterpret_cast<float2*>(g_xp + (size_t)(row0 + 8) * 2048 + col) =
                make_float2(acc[mt][nt4][2], acc[mt][nt4][3]);
        }
    }
}

// ---------------- persistent LSTM kernel (barrier-free) -------
__global__ void __launch_bounds__(NTHREADS, 1)
lstm_persist(const float* __restrict__ c0,
             const float* __restrict__ Whi, const float* __restrict__ Whf,
             const float* __restrict__ Whg, const float* __restrict__ Who,
             float* __restrict__ out)
{
    extern __shared__ char smem_raw[];
    float* Wp  = reinterpret_cast<float*>(smem_raw + SM_WP_OFF);
    float* Asb = reinterpret_cast<float*>(smem_raw + SM_AS_OFF);

    const int tid  = threadIdx.x;
    const int wid  = tid >> 5;          // warp owns batch rows [wid*16, wid*16+16)
    const int lane = tid & 31;
    const int g    = lane >> 2;
    const int t    = lane & 3;
    const int cta  = blockIdx.x;

    const unsigned as_base = (unsigned)__cvta_generic_to_shared(smem_raw) + SM_AS_OFF;

    // one-time: stage recurrent weight slice, tf32, B-fragment order
    {
        const float* Wh[4] = {Whi, Whf, Whg, Who};
        for (int e = tid; e < WP_FLOATS; e += NTHREADS) {
            int j   = e & 1;
            int ln  = (e >> 1) & 31;
            int nt  = (e >> 6) & 3;
            int ksg = e >> 8;
            int jj  = ln >> 2;
            int k   = ksg * 8 + (ln & 3) + 4 * j;
            int col = cta * S_COLS + jj;
            Wp[e] = tf32r(Wh[nt][k * H_ + col]);
        }
    }

    const int col0 = cta * S_COLS + 2 * t;
    const int rb0  = wid * 16 + g;
    const int rb1  = rb0 + 8;
    float creg[4];
    creg[0] = c0[rb0 * H_ + col0];
    creg[1] = c0[rb0 * H_ + col0 + 1];
    creg[2] = c0[rb1 * H_ + col0];
    creg[3] = c0[rb1 * H_ + col0 + 1];

    // prefetch x_proj for step 0
    float2 xpre[4][2];
    #pragma unroll
    for (int nt = 0; nt < 4; ++nt) {
        xpre[nt][0] = __ldcs(reinterpret_cast<const float2*>(
            g_xp + (size_t)rb0 * 2048 + nt * 512 + col0));
        xpre[nt][1] = __ldcs(reinterpret_cast<const float2*>(
            g_xp + (size_t)rb1 * 2048 + nt * 512 + col0));
    }

    __syncthreads();   // Wp ready

    const unsigned* WpU = reinterpret_cast<const unsigned*>(Wp);
    const int swz = g << 3;

    int cur = 0;                        // step % 3
    #pragma unroll 1
    for (int step = 0; step < T_STEPS; ++step) {
        const int nxt = (cur == 2) ? 0 : cur + 1;
        const float* hsrc  = &g_hblk[cur][0][0];
        float*       hnext = &g_hblk[nxt][0][0];
        const unsigned want = (unsigned)step;   // flag >= step -> h_step ready

        // poll: block b ready when CTAs 16b..16b+15 have flag >= step
        auto poll_blk = [&](int b) {
            int src_cta = b * 16 + lane;
            bool skip = (lane >= 16) | (src_cta == cta);  // own cols already fenced
            bool done;
            do {
                unsigned v = skip ? ~0u : ld_acq(&g_flags[src_cta * 32]);
                done = __all_sync(0xffffffffu, v >= want);
            } while (!done);
        };
        // copy: warp's own 16 rows of block b (16 cp16 / lane, coalesced)
        auto issue_blk = [&](int b) {
            const float* src = hsrc + b * AS_BLK_FLOATS + wid * 16 * 128;
            unsigned     dst = as_base + (unsigned)b * 32768u + (unsigned)(wid * 16 * 128) * 4u;
            #pragma unroll
            for (int i = 0; i < 16; ++i) {
                int off = (i * 32 + lane) * 4;
                cp16(dst + (unsigned)off * 4u, src + off);
            }
            asm volatile("cp.async.commit_group;\n" ::: "memory");
        };

        poll_blk(0); issue_blk(0);
        poll_blk(1); issue_blk(1);

        // acc init from prefetched x_proj (bias folded)
        float acc[4][4];
        #pragma unroll
        for (int nt = 0; nt < 4; ++nt) {
            acc[nt][0] = xpre[nt][0].x; acc[nt][1] = xpre[nt][0].y;
            acc[nt][2] = xpre[nt][1].x; acc[nt][3] = xpre[nt][1].y;
        }

        // prefetch x_proj for step+1 (hidden under mma)
        if (step + 1 < T_STEPS) {
            const float* xpn = g_xp + (size_t)(step + 1) * B_ * 2048;
            #pragma unroll
            for (int nt = 0; nt < 4; ++nt) {
                xpre[nt][0] = __ldcs(reinterpret_cast<const float2*>(
                    xpn + (size_t)rb0 * 2048 + nt * 512 + col0));
                xpre[nt][1] = __ldcs(reinterpret_cast<const float2*>(
                    xpn + (size_t)rb1 * 2048 + nt * 512 + col0));
            }
        }

        // mma over 4 k-blocks; depth-2 copy pipeline, polls overlapped
        #pragma unroll 1
        for (int blk = 0; blk < N_BLK; ++blk) {
            if (blk < 2) asm volatile("cp.async.wait_group 1;\n" ::: "memory");
            else if (blk == 2) asm volatile("cp.async.wait_group 1;\n" ::: "memory");
            else asm volatile("cp.async.wait_group 0;\n" ::: "memory");

            const float* Ab = Asb + blk * AS_BLK_FLOATS;
            #pragma unroll 4
            for (int ks = 0; ks < KS_PER_BLK; ++ks) {
                const int kb = ks * 8;
                const int ksg = blk * KS_PER_BLK + ks;
                float2 aA = *reinterpret_cast<const float2*>(
                    Ab + rb0 * 128 + ((kb + 2 * t) ^ swz));
                float2 aB = *reinterpret_cast<const float2*>(
                    Ab + rb1 * 128 + ((kb + 2 * t) ^ swz));
                unsigned a0 = __float_as_uint(aA.x);
                unsigned a1 = __float_as_uint(aB.x);
                unsigned a2 = __float_as_uint(aA.y);
                unsigned a3 = __float_as_uint(aB.y);
                #pragma unroll
                for (int nt = 0; nt < 4; ++nt) {
                    uint2 b2 = *reinterpret_cast<const uint2*>(
                        WpU + ((size_t)(ksg * 4 + nt) * 32 + lane) * 2);
                    mma8(acc[nt], a0, a1, a2, a3, b2.x, b2.y);
                }
            }
            if (blk + 2 < N_BLK) {       // fetch block blk+2 after mma blk
                poll_blk(blk + 2);
                issue_blk(blk + 2);
            }
        }

        // epilogue: gates -> cell -> h (permuted/swizzled, L2-direct)
        #pragma unroll
        for (int ci = 0; ci < 4; ++ci) {
            const int rb  = (ci >= 2) ? rb1 : rb0;
            const int col = col0 + (ci & 1);
            float iv = sigm_(acc[0][ci]);
            float fv = sigm_(acc[1][ci]);
            float gv = tanh_(acc[2][ci]);
            float ov = sigm_(acc[3][ci]);
            float c  = fv * creg[ci] + iv * gv;
            creg[ci] = c;
            float h  = ov * tanh_(c);
            __stcg(hnext + (col >> 7) * AS_BLK_FLOATS + hpos(rb, col), tf32r(h));
            if (step == T_STEPS - 1) {
                out[rb * H_ + col]           = h;
                out[B_ * H_ + rb * H_ + col] = c;
            }
        }

        // publish: all threads fence own stores, then one release-store flag
        __threadfence();
        __syncthreads();
        if (tid == 0) st_rel(&g_flags[cta * 32], (unsigned)(step + 1));

        cur = nxt;
    }
}

// ---------------- launch --------------------------------------
extern "C" void kernel_launch(void* const* d_in, const int* in_sizes, int n_in,
                              void* d_out, int out_size)
{
    const float* x   = (const float*)d_in[0];
    const float* h0  = (const float*)d_in[1];
    const float* c0  = (const float*)d_in[2];
    const float* Wii = (const float*)d_in[3];
    const float* Whi = (const float*)d_in[4];
    const float* bi  = (const float*)d_in[5];
    const float* Wif = (const float*)d_in[6];
    const float* Whf = (const float*)d_in[7];
    const float* bf  = (const float*)d_in[8];
    const float* Wig = (const float*)d_in[9];
    const float* Whg = (const float*)d_in[10];
    const float* bg  = (const float*)d_in[11];
    const float* Wio = (const float*)d_in[12];
    const float* Who = (const float*)d_in[13];
    const float* bo  = (const float*)d_in[14];
    float* out = (float*)d_out;

    cudaFuncSetAttribute(lstm_persist,
                         cudaFuncAttributeMaxDynamicSharedMemorySize, SMEM_BYTES);
    cudaFuncSetAttribute(xproj_gemm,
                         cudaFuncAttributeMaxDynamicSharedMemorySize, GM_SMEM);

    lstm_init<<<64, 256>>>(h0);
    xproj_gemm<<<dim3(32, 512), 256, GM_SMEM>>>(x, Wii, Wif, Wig, Wio,
                                                bi, bf, bg, bo);
    lstm_persist<<<G_CTAS, NTHREADS, SMEM_BYTES>>>(c0, Whi, Whf, Whg, Who, out);
}

// round 9
// speedup vs baseline: 1.3146x; 1.0060x over previous
#include <cuda_runtime.h>
#include <cstdint>

#define T_STEPS 1024
#define B_      64
#define D_      512
#define H_      512

// ---------------- persistent kernel config --------------------
#define G_CTAS   64
#define S_COLS   8
#define NTHREADS 128                  // 4 warps, 16 batch-rows each
#define N_BLK    4                    // k-blocks of 128 h-columns
#define KS_PER_BLK 16

#define WP_FLOATS 16384               // 64 KB recurrent weights (B-fragment order)
#define AS_BLK_FLOATS (B_ * 128)      // 8192 floats = 32 KB per k-block

#define SM_WP_OFF   0
#define SM_AS_OFF   (WP_FLOATS * 4)
#define SMEM_BYTES  (SM_AS_OFF + N_BLK * AS_BLK_FLOATS * 4)   // 196608 B

// ---------------- gemm kernel config --------------------------
#define GM_AS   (128 * 36)
#define GM_BS   (32 * 72)
#define GM_SMEM ((2 * GM_AS + 2 * GM_BS) * 4)

// ---------------- device globals ------------------------------
__device__ __align__(256) float    g_xp[(size_t)T_STEPS * B_ * 4 * H_];
__device__ __align__(256) float    g_hblk[3][N_BLK][AS_BLK_FLOATS];  // triple buffer
__device__ __align__(256) unsigned g_flags[G_CTAS * 32];             // 1 per 128B line

// ---------------- helpers -------------------------------------
__device__ __forceinline__ float tf32r(float x) {
    unsigned r;
    asm("cvt.rna.tf32.f32 %0, %1;" : "=r"(r) : "f"(x));
    return __uint_as_float(r);
}
__device__ __forceinline__ float sigm_(float x) {
    return __fdividef(1.0f, 1.0f + __expf(-x));
}
__device__ __forceinline__ float tanh_(float x) {
    float a = fabsf(x);
    float e = __expf(-2.0f * a);
    float r = __fdividef(1.0f - e, 1.0f + e);
    return copysignf(r, x);
}
__device__ __forceinline__ void mma8(float* acc, unsigned a0, unsigned a1,
                                     unsigned a2, unsigned a3,
                                     unsigned b0, unsigned b1) {
    asm volatile(
        "mma.sync.aligned.m16n8k8.row.col.f32.tf32.tf32.f32 "
        "{%0,%1,%2,%3}, {%4,%5,%6,%7}, {%8,%9}, {%0,%1,%2,%3};"
        : "+f"(acc[0]), "+f"(acc[1]), "+f"(acc[2]), "+f"(acc[3])
        : "r"(a0), "r"(a1), "r"(a2), "r"(a3), "r"(b0), "r"(b1));
}
__device__ __forceinline__ void cp16(unsigned dst, const void* src) {
    asm volatile("cp.async.cg.shared.global [%0], [%1], 16;\n"
                 :: "r"(dst), "l"(src) : "memory");
}
__device__ __forceinline__ unsigned ld_acq(const unsigned* p) {
    unsigned v;
    asm volatile("ld.acquire.gpu.global.u32 %0, [%1];"
                 : "=r"(v) : "l"(p) : "memory");
    return v;
}
__device__ __forceinline__ void st_rel(unsigned* p, unsigned v) {
    asm volatile("st.release.gpu.global.u32 [%0], %1;"
                 :: "l"(p), "r"(v) : "memory");
}
// h storage: within a 128-col block, position kb+2t holds k=kb+t,
// position kb+2t+1 holds k=kb+t+4 (A frag = one LDS.64), XOR-swizzled
// by (row&7)<<3. (R7/R8-verified correct.)
__device__ __forceinline__ int hpos(int row, int col) {
    int o = col & 127;
    int j = o & 7;
    int p = (o & ~7) | ((j < 4) ? (2 * j) : (2 * (j - 4) + 1));
    return row * 128 + (p ^ ((row & 7) << 3));
}

// ---------------- x-projection GEMM + fused init --------------
// grid (32, 512); CTAs with blockIdx.y==0 additionally reset flags and
// convert h0 into the swizzled h buffer (runs before lstm_persist by
// stream order; independent memory, no intra-kernel sync needed).
__global__ void __launch_bounds__(256, 2)
xproj_gemm(const float* __restrict__ x,  const float* __restrict__ h0,
           const float* __restrict__ Wii, const float* __restrict__ Wif,
           const float* __restrict__ Wig, const float* __restrict__ Wio,
           const float* __restrict__ bi,  const float* __restrict__ bf,
           const float* __restrict__ bg,  const float* __restrict__ bo)
{
    extern __shared__ float sm[];
    float* As = sm;
    float* Bs = sm + 2 * GM_AS;

    const int tid  = threadIdx.x;

    // fused init (32 CTAs x 256 threads = 8192 threads)
    if (blockIdx.y == 0) {
        unsigned t0 = blockIdx.x * 256 + tid;
        for (unsigned i = t0; i < G_CTAS * 32; i += 8192) g_flags[i] = 0;
        for (unsigned i = t0; i < B_ * H_; i += 8192) {
            int row = i >> 9, col = i & 511;
            g_hblk[0][col >> 7][hpos(row, col)] = tf32r(h0[i]);
        }
    }

    const int lane = tid & 31;
    const int wid  = tid >> 5;
    const int wm   = wid & 3;
    const int wn   = wid >> 2;
    const int g    = lane >> 2;
    const int t    = lane & 3;

    const int nb = blockIdx.x * 64;
    const int mb = blockIdx.y * 128;
    const int gate = nb >> 9;
    const int colb = nb & 511;

    const float* Wg = (gate == 0) ? Wii : (gate == 1) ? Wif : (gate == 2) ? Wig : Wio;
    const float* bv = (gate == 0) ? bi  : (gate == 1) ? bf  : (gate == 2) ? bg  : bo;

    float acc[2][4][4];
    #pragma unroll
    for (int nt4 = 0; nt4 < 4; ++nt4) {
        float b0 = bv[colb + wn * 32 + nt4 * 8 + 2 * t];
        float b1 = bv[colb + wn * 32 + nt4 * 8 + 2 * t + 1];
        #pragma unroll
        for (int mt = 0; mt < 2; ++mt) {
            acc[mt][nt4][0] = b0; acc[mt][nt4][1] = b1;
            acc[mt][nt4][2] = b0; acc[mt][nt4][3] = b1;
        }
    }

    float4 ra[4], rb[2];
    auto ldAB = [&](int it) {
        #pragma unroll
        for (int i = 0; i < 4; ++i) {
            int idx = tid + i * 256;
            int row = idx >> 3, j4 = idx & 7;
            ra[i] = *reinterpret_cast<const float4*>(
                x + (size_t)(mb + row) * 512 + it * 32 + j4 * 4);
        }
        #pragma unroll
        for (int i = 0; i < 2; ++i) {
            int idx = tid + i * 256;
            int kr = idx >> 4, j4 = idx & 15;
            rb[i] = *reinterpret_cast<const float4*>(
                Wg + (size_t)(it * 32 + kr) * 512 + colb + j4 * 4);
        }
    };
    auto stAB = [&](int buf) {
        #pragma unroll
        for (int i = 0; i < 4; ++i) {
            int idx = tid + i * 256;
            int row = idx >> 3, j4 = idx & 7;
            float4 v = ra[i];
            v.x = tf32r(v.x); v.y = tf32r(v.y); v.z = tf32r(v.z); v.w = tf32r(v.w);
            *reinterpret_cast<float4*>(As + buf * GM_AS + row * 36 + j4 * 4) = v;
        }
        #pragma unroll
        for (int i = 0; i < 2; ++i) {
            int idx = tid + i * 256;
            int kr = idx >> 4, j4 = idx & 15;
            float4 v = rb[i];
            v.x = tf32r(v.x); v.y = tf32r(v.y); v.z = tf32r(v.z); v.w = tf32r(v.w);
            *reinterpret_cast<float4*>(Bs + buf * GM_BS + kr * 72 + j4 * 4) = v;
        }
    };

    ldAB(0);
    stAB(0);
    __syncthreads();

    #pragma unroll 1
    for (int it = 0; it < 16; ++it) {
        if (it < 15) ldAB(it + 1);
        const float* Ab = As + (it & 1) * GM_AS;
        const float* Bb = Bs + (it & 1) * GM_BS;
        #pragma unroll
        for (int ks = 0; ks < 4; ++ks) {
            const int kb = ks * 8;
            unsigned a[2][4], b[4][2];
            #pragma unroll
            for (int mt = 0; mt < 2; ++mt) {
                int rowb = wm * 32 + mt * 16;
                a[mt][0] = __float_as_uint(Ab[(rowb + g)     * 36 + kb + t]);
                a[mt][1] = __float_as_uint(Ab[(rowb + g + 8) * 36 + kb + t]);
                a[mt][2] = __float_as_uint(Ab[(rowb + g)     * 36 + kb + t + 4]);
                a[mt][3] = __float_as_uint(Ab[(rowb + g + 8) * 36 + kb + t + 4]);
            }
            #pragma unroll
            for (int nt4 = 0; nt4 < 4; ++nt4) {
                int cb = wn * 32 + nt4 * 8 + g;
                b[nt4][0] = __float_as_uint(Bb[(kb + t)     * 72 + cb]);
                b[nt4][1] = __float_as_uint(Bb[(kb + t + 4) * 72 + cb]);
            }
            #pragma unroll
            for (int mt = 0; mt < 2; ++mt)
                #pragma unroll
                for (int nt4 = 0; nt4 < 4; ++nt4)
                    mma8(acc[mt][nt4], a[mt][0], a[mt][1], a[mt][2], a[mt][3],
                         b[nt4][0], b[nt4][1]);
        }
        if (it < 15) {
            stAB((it + 1) & 1);
            __syncthreads();
        }
    }

    #pragma unroll
    for (int mt = 0; mt < 2; ++mt) {
        #pragma unroll
        for (int nt4 = 0; nt4 < 4; ++nt4) {
            int row0 = mb + wm * 32 + mt * 16 + g;
            int col  = nb + wn * 32 + nt4 * 8 + 2 * t;
            *reinterpret_cast<float2*>(g_xp + (size_t)row0 * 2048 + col) =
                make_float2(acc[mt][nt4][0], acc[mt][nt4][1]);
            *reinterpret_cast<float2*>(g_xp + (size_t)(row0 + 8) * 2048 + col) =
                make_float2(acc[mt][nt4][2], acc[mt][nt4][3]);
        }
    }
}

// ---------------- persistent LSTM kernel (barrier-free) -------
__global__ void __launch_bounds__(NTHREADS, 1)
lstm_persist(const float* __restrict__ c0,
             const float* __restrict__ Whi, const float* __restrict__ Whf,
             const float* __restrict__ Whg, const float* __restrict__ Who,
             float* __restrict__ out)
{
    extern __shared__ char smem_raw[];
    float* Wp  = reinterpret_cast<float*>(smem_raw + SM_WP_OFF);
    float* Asb = reinterpret_cast<float*>(smem_raw + SM_AS_OFF);

    const int tid  = threadIdx.x;
    const int wid  = tid >> 5;          // warp owns batch rows [wid*16, wid*16+16)
    const int lane = tid & 31;
    const int g    = lane >> 2;
    const int t    = lane & 3;
    const int cta  = blockIdx.x;

    const unsigned as_base = (unsigned)__cvta_generic_to_shared(smem_raw) + SM_AS_OFF;

    // one-time: stage recurrent weight slice, tf32, B-fragment order
    {
        const float* Wh[4] = {Whi, Whf, Whg, Who};
        for (int e = tid; e < WP_FLOATS; e += NTHREADS) {
            int j   = e & 1;
            int ln  = (e >> 1) & 31;
            int nt  = (e >> 6) & 3;
            int ksg = e >> 8;
            int jj  = ln >> 2;
            int k   = ksg * 8 + (ln & 3) + 4 * j;
            int col = cta * S_COLS + jj;
            Wp[e] = tf32r(Wh[nt][k * H_ + col]);
        }
    }

    const int col0 = cta * S_COLS + 2 * t;
    const int rb0  = wid * 16 + g;
    const int rb1  = rb0 + 8;
    float creg[4];
    creg[0] = c0[rb0 * H_ + col0];
    creg[1] = c0[rb0 * H_ + col0 + 1];
    creg[2] = c0[rb1 * H_ + col0];
    creg[3] = c0[rb1 * H_ + col0 + 1];

    // prefetch x_proj for step 0
    float2 xpre[4][2];
    #pragma unroll
    for (int nt = 0; nt < 4; ++nt) {
        xpre[nt][0] = __ldcs(reinterpret_cast<const float2*>(
            g_xp + (size_t)rb0 * 2048 + nt * 512 + col0));
        xpre[nt][1] = __ldcs(reinterpret_cast<const float2*>(
            g_xp + (size_t)rb1 * 2048 + nt * 512 + col0));
    }

    __syncthreads();   // Wp ready

    const unsigned* WpU = reinterpret_cast<const unsigned*>(Wp);
    const int swz = g << 3;

    int cur = 0;                        // step % 3
    #pragma unroll 1
    for (int step = 0; step < T_STEPS; ++step) {
        const int nxt = (cur == 2) ? 0 : cur + 1;
        const float* hsrc  = &g_hblk[cur][0][0];
        float*       hnext = &g_hblk[nxt][0][0];
        const unsigned want = (unsigned)step;   // flag >= step -> h_step ready

        // poll pair of blocks {2p, 2p+1}: gated by CTAs [32p, 32p+32)
        auto poll2 = [&](int p) {
            int src_cta = p * 32 + lane;
            bool skip = (src_cta == cta);       // own cols fenced by own publish
            bool done;
            do {
                unsigned v = skip ? ~0u : ld_acq(&g_flags[src_cta * 32]);
                done = __all_sync(0xffffffffu, v >= want);
            } while (!done);
        };
        // copy: warp's own 16 rows of block b (16 cp16 / lane, coalesced)
        auto issue_blk = [&](int b) {
            const float* src = hsrc + b * AS_BLK_FLOATS + wid * 16 * 128;
            unsigned     dst = as_base + (unsigned)b * 32768u + (unsigned)(wid * 16 * 128) * 4u;
            #pragma unroll
            for (int i = 0; i < 16; ++i) {
                int off = (i * 32 + lane) * 4;
                cp16(dst + (unsigned)off * 4u, src + off);
            }
            asm volatile("cp.async.commit_group;\n" ::: "memory");
        };

        // acc init from prefetched x_proj (bias folded)
        float acc[4][4];
        #pragma unroll
        for (int nt = 0; nt < 4; ++nt) {
            acc[nt][0] = xpre[nt][0].x; acc[nt][1] = xpre[nt][0].y;
            acc[nt][2] = xpre[nt][1].x; acc[nt][3] = xpre[nt][1].y;
        }
        // prefetch x_proj for step+1 FIRST (LDGs fly during the polls below)
        if (step + 1 < T_STEPS) {
            const float* xpn = g_xp + (size_t)(step + 1) * B_ * 2048;
            #pragma unroll
            for (int nt = 0; nt < 4; ++nt) {
                xpre[nt][0] = __ldcs(reinterpret_cast<const float2*>(
                    xpn + (size_t)rb0 * 2048 + nt * 512 + col0));
                xpre[nt][1] = __ldcs(reinterpret_cast<const float2*>(
                    xpn + (size_t)rb1 * 2048 + nt * 512 + col0));
            }
        }

        poll2(0);                       // blocks 0,1 ready
        issue_blk(0);                   // group 0
        issue_blk(1);                   // group 1

        // mma over 4 k-blocks; copy pipeline depth 2; poll for 2,3 after blk0
        #pragma unroll 1
        for (int blk = 0; blk < N_BLK; ++blk) {
            switch (blk) {
                case 0: asm volatile("cp.async.wait_group 1;\n" ::: "memory"); break;
                case 1: asm volatile("cp.async.wait_group 2;\n" ::: "memory"); break;
                case 2: asm volatile("cp.async.wait_group 1;\n" ::: "memory"); break;
                default: asm volatile("cp.async.wait_group 0;\n" ::: "memory"); break;
            }
            const float* Ab = Asb + blk * AS_BLK_FLOATS;
            #pragma unroll 4
            for (int ks = 0; ks < KS_PER_BLK; ++ks) {
                const int kb = ks * 8;
                const int ksg = blk * KS_PER_BLK + ks;
                float2 aA = *reinterpret_cast<const float2*>(
                    Ab + rb0 * 128 + ((kb + 2 * t) ^ swz));
                float2 aB = *reinterpret_cast<const float2*>(
                    Ab + rb1 * 128 + ((kb + 2 * t) ^ swz));
                unsigned a0 = __float_as_uint(aA.x);
                unsigned a1 = __float_as_uint(aB.x);
                unsigned a2 = __float_as_uint(aA.y);
                unsigned a3 = __float_as_uint(aB.y);
                #pragma unroll
                for (int nt = 0; nt < 4; ++nt) {
                    uint2 b2 = *reinterpret_cast<const uint2*>(
                        WpU + ((size_t)(ksg * 4 + nt) * 32 + lane) * 2);
                    mma8(acc[nt], a0, a1, a2, a3, b2.x, b2.y);
                }
            }
            if (blk == 0) {              // fetch blocks 2,3 after first mma block
                poll2(1);
                issue_blk(2);            // group 2
                issue_blk(3);            // group 3
            }
        }

        // epilogue: gates -> cell -> h (permuted/swizzled, L2-direct)
        #pragma unroll
        for (int ci = 0; ci < 4; ++ci) {
            const int rb  = (ci >= 2) ? rb1 : rb0;
            const int col = col0 + (ci & 1);
            float iv = sigm_(acc[0][ci]);
            float fv = sigm_(acc[1][ci]);
            float gv = tanh_(acc[2][ci]);
            float ov = sigm_(acc[3][ci]);
            float c  = fv * creg[ci] + iv * gv;
            creg[ci] = c;
            float h  = ov * tanh_(c);
            __stcg(hnext + (col >> 7) * AS_BLK_FLOATS + hpos(rb, col), tf32r(h));
            if (step == T_STEPS - 1) {
                out[rb * H_ + col]           = h;
                out[B_ * H_ + rb * H_ + col] = c;
            }
        }

        // publish: barrier gives happens-before; ONE cumulative fence + release
        __syncthreads();
        if (tid == 0) {
            __threadfence();
            st_rel(&g_flags[cta * 32], (unsigned)(step + 1));
        }

        cur = nxt;
    }
}

// ---------------- launch --------------------------------------
extern "C" void kernel_launch(void* const* d_in, const int* in_sizes, int n_in,
                              void* d_out, int out_size)
{
    const float* x   = (const float*)d_in[0];
    const float* h0  = (const float*)d_in[1];
    const float* c0  = (const float*)d_in[2];
    const float* Wii = (const float*)d_in[3];
    const float* Whi = (const float*)d_in[4];
    const float* bi  = (const float*)d_in[5];
    const float* Wif = (const float*)d_in[6];
    const float* Whf = (const float*)d_in[7];
    const float* bf  = (const float*)d_in[8];
    const float* Wig = (const float*)d_in[9];
    const float* Whg = (const float*)d_in[10];
    const float* bg  = (const float*)d_in[11];
    const float* Wio = (const float*)d_in[12];
    const float* Who = (const float*)d_in[13];
    const float* bo  = (const float*)d_in[14];
    float* out = (float*)d_out;

    cudaFuncSetAttribute(lstm_persist,
                         cudaFuncAttributeMaxDynamicSharedMemorySize, SMEM_BYTES);
    cudaFuncSetAttribute(xproj_gemm,
                         cudaFuncAttributeMaxDynamicSharedMemorySize, GM_SMEM);

    xproj_gemm<<<dim3(32, 512), 256, GM_SMEM>>>(x, h0, Wii, Wif, Wig, Wio,
                                                bi, bf, bg, bo);
    lstm_persist<<<G_CTAS, NTHREADS, SMEM_BYTES>>>(c0, Whi, Whf, Whg, Who, out);
}

// round 11
// speedup vs baseline: 1.4941x; 1.1365x over previous
#include <cuda_runtime.h>
#include <cstdint>

#define T_STEPS 1024
#define B_      64
#define D_      512
#define H_      512

// ---------------- persistent kernel config --------------------
#define G_CTAS   64
#define S_COLS   8
#define NTHREADS 256                  // 8 warps: 4 row-groups x 2 k-halves
#define N_BLK    4                    // k-blocks of 128 h-columns
#define KS_PER_BLK 16

#define WP_FLOATS 16384               // 64 KB recurrent weights (B-fragment order)
#define AS_BLK_FLOATS (B_ * 128)      // 8192 floats = 32 KB per k-block

#define SM_WP_OFF   0
#define SM_AS_OFF   (WP_FLOATS * 4)                           // 65536
#define SM_PB_OFF   (SM_AS_OFF + N_BLK * AS_BLK_FLOATS * 4)   // 196608
#define PB_STRIDE   20                                        // floats, pad vs conflicts
#define SMEM_BYTES  (SM_PB_OFF + 2 * 128 * PB_STRIDE * 4)     // 217088 B

// ---------------- gemm kernel config --------------------------
#define GM_AS   (128 * 36)
#define GM_BS   (32 * 72)
#define GM_SMEM ((2 * GM_AS + 2 * GM_BS) * 4)

// ---------------- device globals ------------------------------
__device__ __align__(256) float    g_xp[(size_t)T_STEPS * B_ * 4 * H_];
__device__ __align__(256) float    g_hblk[3][N_BLK][AS_BLK_FLOATS];  // triple buffer
__device__ __align__(256) unsigned g_flags[G_CTAS * 32];             // 1 per 128B line

// ---------------- helpers -------------------------------------
__device__ __forceinline__ float tf32r(float x) {
    unsigned r;
    asm("cvt.rna.tf32.f32 %0, %1;" : "=r"(r) : "f"(x));
    return __uint_as_float(r);
}
__device__ __forceinline__ float sigm_(float x) {
    return __fdividef(1.0f, 1.0f + __expf(-x));
}
__device__ __forceinline__ float tanh_(float x) {
    float a = fabsf(x);
    float e = __expf(-2.0f * a);
    float r = __fdividef(1.0f - e, 1.0f + e);
    return copysignf(r, x);
}
__device__ __forceinline__ void mma8(float* acc, unsigned a0, unsigned a1,
                                     unsigned a2, unsigned a3,
                                     unsigned b0, unsigned b1) {
    asm volatile(
        "mma.sync.aligned.m16n8k8.row.col.f32.tf32.tf32.f32 "
        "{%0,%1,%2,%3}, {%4,%5,%6,%7}, {%8,%9}, {%0,%1,%2,%3};"
        : "+f"(acc[0]), "+f"(acc[1]), "+f"(acc[2]), "+f"(acc[3])
        : "r"(a0), "r"(a1), "r"(a2), "r"(a3), "r"(b0), "r"(b1));
}
__device__ __forceinline__ void cp16(unsigned dst, const void* src) {
    asm volatile("cp.async.cg.shared.global [%0], [%1], 16;\n"
                 :: "r"(dst), "l"(src) : "memory");
}
__device__ __forceinline__ unsigned ld_acq(const unsigned* p) {
    unsigned v;
    asm volatile("ld.acquire.gpu.global.u32 %0, [%1];"
                 : "=r"(v) : "l"(p) : "memory");
    return v;
}
__device__ __forceinline__ void st_rel(unsigned* p, unsigned v) {
    asm volatile("st.release.gpu.global.u32 [%0], %1;"
                 :: "l"(p), "r"(v) : "memory");
}
// h storage: within a 128-col block, position kb+2t holds k=kb+t,
// position kb+2t+1 holds k=kb+t+4 (A frag = one LDS.64), XOR-swizzled
// by (row&7)<<3. (R7-R9 verified.)
__device__ __forceinline__ int hpos(int row, int col) {
    int o = col & 127;
    int j = o & 7;
    int p = (o & ~7) | ((j < 4) ? (2 * j) : (2 * (j - 4) + 1));
    return row * 128 + (p ^ ((row & 7) << 3));
}

// ---------------- x-projection GEMM + fused init (R9-proven) --
__global__ void __launch_bounds__(256, 2)
xproj_gemm(const float* __restrict__ x,  const float* __restrict__ h0,
           const float* __restrict__ Wii, const float* __restrict__ Wif,
           const float* __restrict__ Wig, const float* __restrict__ Wio,
           const float* __restrict__ bi,  const float* __restrict__ bf,
           const float* __restrict__ bg,  const float* __restrict__ bo)
{
    extern __shared__ float sm[];
    float* As = sm;
    float* Bs = sm + 2 * GM_AS;

    const int tid  = threadIdx.x;

    if (blockIdx.y == 0) {
        unsigned t0 = blockIdx.x * 256 + tid;
        for (unsigned i = t0; i < G_CTAS * 32; i += 8192) g_flags[i] = 0;
        for (unsigned i = t0; i < B_ * H_; i += 8192) {
            int row = i >> 9, col = i & 511;
            g_hblk[0][col >> 7][hpos(row, col)] = tf32r(h0[i]);
        }
    }

    const int lane = tid & 31;
    const int wid  = tid >> 5;
    const int wm   = wid & 3;
    const int wn   = wid >> 2;
    const int g    = lane >> 2;
    const int t    = lane & 3;

    const int nb = blockIdx.x * 64;
    const int mb = blockIdx.y * 128;
    const int gate = nb >> 9;
    const int colb = nb & 511;

    const float* Wg = (gate == 0) ? Wii : (gate == 1) ? Wif : (gate == 2) ? Wig : Wio;
    const float* bv = (gate == 0) ? bi  : (gate == 1) ? bf  : (gate == 2) ? bg  : bo;

    float acc[2][4][4];
    #pragma unroll
    for (int nt4 = 0; nt4 < 4; ++nt4) {
        float b0 = bv[colb + wn * 32 + nt4 * 8 + 2 * t];
        float b1 = bv[colb + wn * 32 + nt4 * 8 + 2 * t + 1];
        #pragma unroll
        for (int mt = 0; mt < 2; ++mt) {
            acc[mt][nt4][0] = b0; acc[mt][nt4][1] = b1;
            acc[mt][nt4][2] = b0; acc[mt][nt4][3] = b1;
        }
    }

    float4 ra[4], rb[2];
    auto ldAB = [&](int it) {
        #pragma unroll
        for (int i = 0; i < 4; ++i) {
            int idx = tid + i * 256;
            int row = idx >> 3, j4 = idx & 7;
            ra[i] = *reinterpret_cast<const float4*>(
                x + (size_t)(mb + row) * 512 + it * 32 + j4 * 4);
        }
        #pragma unroll
        for (int i = 0; i < 2; ++i) {
            int idx = tid + i * 256;
            int kr = idx >> 4, j4 = idx & 15;
            rb[i] = *reinterpret_cast<const float4*>(
                Wg + (size_t)(it * 32 + kr) * 512 + colb + j4 * 4);
        }
    };
    auto stAB = [&](int buf) {
        #pragma unroll
        for (int i = 0; i < 4; ++i) {
            int idx = tid + i * 256;
            int row = idx >> 3, j4 = idx & 7;
            float4 v = ra[i];
            v.x = tf32r(v.x); v.y = tf32r(v.y); v.z = tf32r(v.z); v.w = tf32r(v.w);
            *reinterpret_cast<float4*>(As + buf * GM_AS + row * 36 + j4 * 4) = v;
        }
        #pragma unroll
        for (int i = 0; i < 2; ++i) {
            int idx = tid + i * 256;
            int kr = idx >> 4, j4 = idx & 15;
            float4 v = rb[i];
            v.x = tf32r(v.x); v.y = tf32r(v.y); v.z = tf32r(v.z); v.w = tf32r(v.w);
            *reinterpret_cast<float4*>(Bs + buf * GM_BS + kr * 72 + j4 * 4) = v;
        }
    };

    ldAB(0);
    stAB(0);
    __syncthreads();

    #pragma unroll 1
    for (int it = 0; it < 16; ++it) {
        if (it < 15) ldAB(it + 1);
        const float* Ab = As + (it & 1) * GM_AS;
        const float* Bb = Bs + (it & 1) * GM_BS;
        #pragma unroll
        for (int ks = 0; ks < 4; ++ks) {
            const int kb = ks * 8;
            unsigned a[2][4], b[4][2];
            #pragma unroll
            for (int mt = 0; mt < 2; ++mt) {
                int rowb = wm * 32 + mt * 16;
                a[mt][0] = __float_as_uint(Ab[(rowb + g)     * 36 + kb + t]);
                a[mt][1] = __float_as_uint(Ab[(rowb + g + 8) * 36 + kb + t]);
                a[mt][2] = __float_as_uint(Ab[(rowb + g)     * 36 + kb + t + 4]);
                a[mt][3] = __float_as_uint(Ab[(rowb + g + 8) * 36 + kb + t + 4]);
            }
            #pragma unroll
            for (int nt4 = 0; nt4 < 4; ++nt4) {
                int cb = wn * 32 + nt4 * 8 + g;
                b[nt4][0] = __float_as_uint(Bb[(kb + t)     * 72 + cb]);
                b[nt4][1] = __float_as_uint(Bb[(kb + t + 4) * 72 + cb]);
            }
            #pragma unroll
            for (int mt = 0; mt < 2; ++mt)
                #pragma unroll
                for (int nt4 = 0; nt4 < 4; ++nt4)
                    mma8(acc[mt][nt4], a[mt][0], a[mt][1], a[mt][2], a[mt][3],
                         b[nt4][0], b[nt4][1]);
        }
        if (it < 15) {
            stAB((it + 1) & 1);
            __syncthreads();
        }
    }

    #pragma unroll
    for (int mt = 0; mt < 2; ++mt) {
        #pragma unroll
        for (int nt4 = 0; nt4 < 4; ++nt4) {
            int row0 = mb + wm * 32 + mt * 16 + g;
            int col  = nb + wn * 32 + nt4 * 8 + 2 * t;
            *reinterpret_cast<float2*>(g_xp + (size_t)row0 * 2048 + col) =
                make_float2(acc[mt][nt4][0], acc[mt][nt4][1]);
            *reinterpret_cast<float2*>(g_xp + (size_t)(row0 + 8) * 2048 + col) =
                make_float2(acc[mt][nt4][2], acc[mt][nt4][3]);
        }
    }
}

// ---------------- persistent LSTM kernel (8 warps, k-split) ---
__global__ void __launch_bounds__(NTHREADS, 1)
lstm_persist(const float* __restrict__ c0,
             const float* __restrict__ Whi, const float* __restrict__ Whf,
             const float* __restrict__ Whg, const float* __restrict__ Who,
             float* __restrict__ out)
{
    extern __shared__ char smem_raw[];
    float* Wp   = reinterpret_cast<float*>(smem_raw + SM_WP_OFF);
    float* Asb  = reinterpret_cast<float*>(smem_raw + SM_AS_OFF);
    float* Pbuf = reinterpret_cast<float*>(smem_raw + SM_PB_OFF);

    const int tid  = threadIdx.x;
    const int wid  = tid >> 5;
    const int lane = tid & 31;
    const int half = wid >> 2;          // 0: k[0,256), 1: k[256,512)
    const int wrow = wid & 3;           // row-group: rows [wrow*16, wrow*16+16)
    const int g    = lane >> 2;
    const int t    = lane & 3;
    const int cta  = blockIdx.x;

    const unsigned as_base = (unsigned)__cvta_generic_to_shared(smem_raw) + SM_AS_OFF;

    // one-time: stage recurrent weight slice, tf32, B-fragment order
    {
        const float* Wh[4] = {Whi, Whf, Whg, Who};
        for (int e = tid; e < WP_FLOATS; e += NTHREADS) {
            int j   = e & 1;
            int ln  = (e >> 1) & 31;
            int nt  = (e >> 6) & 3;
            int ksg = e >> 8;
            int jj  = ln >> 2;
            int k   = ksg * 8 + (ln & 3) + 4 * j;
            int col = cta * S_COLS + jj;
            Wp[e] = tf32r(Wh[nt][k * H_ + col]);
        }
    }

    const int col0 = cta * S_COLS + 2 * t;
    const int rb0  = wrow * 16 + g;
    const int rb1  = rb0 + 8;

    float creg[4];
    float2 xpre[4][2];
    if (half == 0) {
        creg[0] = c0[rb0 * H_ + col0];
        creg[1] = c0[rb0 * H_ + col0 + 1];
        creg[2] = c0[rb1 * H_ + col0];
        creg[3] = c0[rb1 * H_ + col0 + 1];
        #pragma unroll
        for (int nt = 0; nt < 4; ++nt) {
            xpre[nt][0] = __ldcs(reinterpret_cast<const float2*>(
                g_xp + (size_t)rb0 * 2048 + nt * 512 + col0));
            xpre[nt][1] = __ldcs(reinterpret_cast<const float2*>(
                g_xp + (size_t)rb1 * 2048 + nt * 512 + col0));
        }
    }

    __syncthreads();   // Wp ready

    const unsigned* WpU = reinterpret_cast<const unsigned*>(Wp);
    const int swz  = g << 3;
    const int pidx = wrow * 32 + lane;  // partial-buffer slot (matches across halves)

    int cur = 0;                        // step % 3
    #pragma unroll 1
    for (int step = 0; step < T_STEPS; ++step) {
        const int nxt = (cur == 2) ? 0 : cur + 1;
        const float* hsrc  = &g_hblk[cur][0][0];
        float*       hnext = &g_hblk[nxt][0][0];
        const unsigned want = (unsigned)step;

        // poll this half's gating CTAs (one 32-flag round per warp)
        {
            int src_cta = half * 32 + lane;
            bool skip = (src_cta == cta);
            bool done;
            do {
                unsigned v = skip ? ~0u : ld_acq(&g_flags[src_cta * 32]);
                done = __all_sync(0xffffffffu, v >= want);
            } while (!done);
        }

        // copy this warp's rows of its 2 k-blocks (16 cp16/lane each)
        #pragma unroll
        for (int i2 = 0; i2 < 2; ++i2) {
            int b = half * 2 + i2;
            const float* src = hsrc + b * AS_BLK_FLOATS + wrow * 16 * 128;
            unsigned     dst = as_base + (unsigned)b * 32768u
                               + (unsigned)(wrow * 16 * 128) * 4u;
            #pragma unroll
            for (int i = 0; i < 16; ++i) {
                int off = (i * 32 + lane) * 4;
                cp16(dst + (unsigned)off * 4u, src + off);
            }
            asm volatile("cp.async.commit_group;\n" ::: "memory");
        }

        // acc init: half 0 from x_proj (bias folded), half 1 zero
        float acc[4][4];
        if (half == 0) {
            #pragma unroll
            for (int nt = 0; nt < 4; ++nt) {
                acc[nt][0] = xpre[nt][0].x; acc[nt][1] = xpre[nt][0].y;
                acc[nt][2] = xpre[nt][1].x; acc[nt][3] = xpre[nt][1].y;
            }
            if (step + 1 < T_STEPS) {   // prefetch next step's x_proj
                const float* xpn = g_xp + (size_t)(step + 1) * B_ * 2048;
                #pragma unroll
                for (int nt = 0; nt < 4; ++nt) {
                    xpre[nt][0] = __ldcs(reinterpret_cast<const float2*>(
                        xpn + (size_t)rb0 * 2048 + nt * 512 + col0));
                    xpre[nt][1] = __ldcs(reinterpret_cast<const float2*>(
                        xpn + (size_t)rb1 * 2048 + nt * 512 + col0));
                }
            }
        } else {
            #pragma unroll
            for (int nt = 0; nt < 4; ++nt)
                #pragma unroll
                for (int ci = 0; ci < 4; ++ci) acc[nt][ci] = 0.0f;
        }

        // mma over this warp's 2 k-blocks
        #pragma unroll
        for (int i2 = 0; i2 < 2; ++i2) {
            if (i2 == 0) asm volatile("cp.async.wait_group 1;\n" ::: "memory");
            else         asm volatile("cp.async.wait_group 0;\n" ::: "memory");
            const int blk = half * 2 + i2;
            const float* Ab = Asb + blk * AS_BLK_FLOATS;
            #pragma unroll 4
            for (int ks = 0; ks < KS_PER_BLK; ++ks) {
                const int kb = ks * 8;
                const int ksg = blk * KS_PER_BLK + ks;
                float2 aA = *reinterpret_cast<const float2*>(
                    Ab + rb0 * 128 + ((kb + 2 * t) ^ swz));
                float2 aB = *reinterpret_cast<const float2*>(
                    Ab + rb1 * 128 + ((kb + 2 * t) ^ swz));
                unsigned a0 = __float_as_uint(aA.x);
                unsigned a1 = __float_as_uint(aB.x);
                unsigned a2 = __float_as_uint(aA.y);
                unsigned a3 = __float_as_uint(aB.y);
                #pragma unroll
                for (int nt = 0; nt < 4; ++nt) {
                    uint2 b2 = *reinterpret_cast<const uint2*>(
                        WpU + ((size_t)(ksg * 4 + nt) * 32 + lane) * 2);
                    mma8(acc[nt], a0, a1, a2, a3, b2.x, b2.y);
                }
            }
        }

        // half 1: deposit partials (double-buffered, padded, float4)
        float* pb = Pbuf + (step & 1) * 128 * PB_STRIDE + pidx * PB_STRIDE;
        if (half == 1) {
            #pragma unroll
            for (int nt = 0; nt < 4; ++nt)
                *reinterpret_cast<float4*>(pb + nt * 4) =
                    make_float4(acc[nt][0], acc[nt][1], acc[nt][2], acc[nt][3]);
        }

        __syncthreads();   // partials(step) visible; rendezvous of both halves

        if (half == 0) {
            // reduce + epilogue
            #pragma unroll
            for (int nt = 0; nt < 4; ++nt) {
                float4 p = *reinterpret_cast<const float4*>(pb + nt * 4);
                acc[nt][0] += p.x; acc[nt][1] += p.y;
                acc[nt][2] += p.z; acc[nt][3] += p.w;
            }
            #pragma unroll
            for (int ci = 0; ci < 4; ++ci) {
                const int rb  = (ci >= 2) ? rb1 : rb0;
                const int col = col0 + (ci & 1);
                float iv = sigm_(acc[0][ci]);
                float fv = sigm_(acc[1][ci]);
                float gv = tanh_(acc[2][ci]);
                float ov = sigm_(acc[3][ci]);
                float c  = fv * creg[ci] + iv * gv;
                creg[ci] = c;
                float h  = ov * tanh_(c);
                __stcg(hnext + (col >> 7) * AS_BLK_FLOATS + hpos(rb, col), tf32r(h));
                if (step == T_STEPS - 1) {
                    out[rb * H_ + col]           = h;
                    out[B_ * H_ + rb * H_ + col] = c;
                }
            }
            // publish: HB among warps 0-3, then one fence + release flag
            asm volatile("bar.sync 1, 128;" ::: "memory");
            if (tid == 0) {
                __threadfence();
                st_rel(&g_flags[cta * 32], (unsigned)(step + 1));
            }
        }

        cur = nxt;
    }
}

// ---------------- launch --------------------------------------
extern "C" void kernel_launch(void* const* d_in, const int* in_sizes, int n_in,
                              void* d_out, int out_size)
{
    const float* x   = (const float*)d_in[0];
    const float* h0  = (const float*)d_in[1];
    const float* c0  = (const float*)d_in[2];
    const float* Wii = (const float*)d_in[3];
    const float* Whi = (const float*)d_in[4];
    const float* bi  = (const float*)d_in[5];
    const float* Wif = (const float*)d_in[6];
    const float* Whf = (const float*)d_in[7];
    const float* bf  = (const float*)d_in[8];
    const float* Wig = (const float*)d_in[9];
    const float* Whg = (const float*)d_in[10];
    const float* bg  = (const float*)d_in[11];
    const float* Wio = (const float*)d_in[12];
    const float* Who = (const float*)d_in[13];
    const float* bo  = (const float*)d_in[14];
    float* out = (float*)d_out;

    cudaFuncSetAttribute(lstm_persist,
                         cudaFuncAttributeMaxDynamicSharedMemorySize, SMEM_BYTES);
    cudaFuncSetAttribute(xproj_gemm,
                         cudaFuncAttributeMaxDynamicSharedMemorySize, GM_SMEM);

    xproj_gemm<<<dim3(32, 512), 256, GM_SMEM>>>(x, h0, Wii, Wif, Wig, Wio,
                                                bi, bf, bg, bo);
    lstm_persist<<<G_CTAS, NTHREADS, SMEM_BYTES>>>(c0, Whi, Whf, Whg, Who, out);
}